// round 1
// baseline (speedup 1.0000x reference)
#include <cuda_runtime.h>

#define BB 16
#define CC 64
#define OO 64
#define HH 256
#define WW 256
#define MX 32
#define MY 32

#define TWOPI 6.28318530717958647692f

// Scratch (no allocation allowed -> __device__ globals)
__device__ float2 g_A[BB*CC*MY*HH];   // [bc][ky][h]      67 MB
__device__ float2 g_X[BB*MX*MY*CC];   // [b][mode][c]     8.4 MB
__device__ float2 g_M[BB*OO*MX*MY];   // [bo][mode]       8.4 MB
__device__ float2 g_T[BB*OO*HH*MY];   // [bo][h][ky]      67 MB

// ---------------------------------------------------------------------------
// K1: forward W-transform.  A[bc,ky,h] = (1/256) * sum_w x[bc,h,w] e^{-2pi i ky w/256}
// grid (1024, 8), block 128.  Warp lanes = ky (0..31), each thread 8 h-rows.
// x loads are warp-broadcast float4; twiddle via register recurrence.
// ---------------------------------------------------------------------------
__global__ __launch_bounds__(128) void k_fwdW(const float* __restrict__ x) {
    int bc = blockIdx.x;
    int h0 = blockIdx.y * 32;

    __shared__ float xs[32 * 256];       // 32 KB
    __shared__ float2 st[32][33];        // staging for coalesced transpose store

    const float* xp = x + (size_t)bc * HH * WW + (size_t)h0 * WW;
    for (int i = threadIdx.x; i < 32 * 256; i += 128) xs[i] = xp[i];
    __syncthreads();

    int lane = threadIdx.x & 31;     // ky
    int wrp  = threadIdx.x >> 5;     // 0..3
    int ky   = lane;
    int r0   = wrp * 8;

    float ar[8], ai[8];
    #pragma unroll
    for (int j = 0; j < 8; j++) { ar[j] = 0.f; ai[j] = 0.f; }

    float ds, dc;
    sincosf(-TWOPI * (float)ky / 256.0f, &ds, &dc);
    float cw = 1.0f, sw = 0.0f;      // (cos, sin) of -2pi ky w / 256

    for (int w4 = 0; w4 < 256; w4 += 4) {
        float xc[8][4];
        #pragma unroll
        for (int j = 0; j < 8; j++) {
            float4 v = *reinterpret_cast<const float4*>(&xs[(r0 + j) * 256 + w4]);
            xc[j][0] = v.x; xc[j][1] = v.y; xc[j][2] = v.z; xc[j][3] = v.w;
        }
        #pragma unroll
        for (int u = 0; u < 4; u++) {
            #pragma unroll
            for (int j = 0; j < 8; j++) {
                ar[j] = fmaf(xc[j][u], cw, ar[j]);
                ai[j] = fmaf(xc[j][u], sw, ai[j]);
            }
            float t = cw * dc - sw * ds;
            sw = fmaf(sw, dc, cw * ds);
            cw = t;
        }
    }

    const float sc = 1.0f / 256.0f;  // ortho forward
    #pragma unroll
    for (int j = 0; j < 8; j++)
        st[ky][r0 + j] = make_float2(ar[j] * sc, ai[j] * sc);
    __syncthreads();

    // coalesced write: each warp writes 8 ky-rows of 32 consecutive h
    for (int kq = 0; kq < 8; kq++) {
        int kyy = wrp * 8 + kq;
        g_A[((size_t)bc * 32 + kyy) * 256 + h0 + lane] = st[kyy][lane];
    }
}

// ---------------------------------------------------------------------------
// K2: forward H-transform.  X[b,kx*32+ky,c] = sum_h A[bc,ky,h] e^{-2pi i kx h/256}
// grid (1024, 2 ky-halves), block 256. lanes = kx, warp -> 2 ky.
// ---------------------------------------------------------------------------
__global__ __launch_bounds__(256) void k_fwdH() {
    int bc  = blockIdx.x;
    int kyh = blockIdx.y;            // 0/1 -> ky base 0/16

    __shared__ float2 As[16 * 256];  // 32 KB
    const float2* ap = &g_A[((size_t)bc * 32 + kyh * 16) * 256];
    for (int i = threadIdx.x; i < 16 * 256; i += 256) As[i] = ap[i];
    __syncthreads();

    int lane = threadIdx.x & 31;     // kx
    int wrp  = threadIdx.x >> 5;     // 0..7 -> ky pair
    int kx   = lane;
    int kyl  = wrp * 2;

    float xr0 = 0, xi0 = 0, xr1 = 0, xi1 = 0;
    float ds, dc;
    sincosf(-TWOPI * (float)kx / 256.0f, &ds, &dc);
    float cw = 1.0f, sw = 0.0f;

    for (int h = 0; h < 256; h++) {
        float2 a0 = As[kyl * 256 + h];         // broadcast
        float2 a1 = As[(kyl + 1) * 256 + h];   // broadcast
        // X += A * (cw + i sw)
        xr0 = fmaf(a0.x, cw, fmaf(-a0.y, sw, xr0));
        xi0 = fmaf(a0.x, sw, fmaf( a0.y, cw, xi0));
        xr1 = fmaf(a1.x, cw, fmaf(-a1.y, sw, xr1));
        xi1 = fmaf(a1.x, sw, fmaf( a1.y, cw, xi1));
        float t = cw * dc - sw * ds;
        sw = fmaf(sw, dc, cw * ds);
        cw = t;
    }

    int b = bc >> 6, c = bc & 63;
    int ky = kyh * 16 + kyl;
    g_X[((size_t)b * 1024 + kx * 32 + ky    ) * 64 + c] = make_float2(xr0, xi0);
    g_X[((size_t)b * 1024 + kx * 32 + ky + 1) * 64 + c] = make_float2(xr1, xi1);
}

// ---------------------------------------------------------------------------
// K3: channel mix.  M[b,o,m] = sum_c X[b,c,m] * (Wr + i Wi)[c,o,m]
// grid (1024 modes), block 256. Weight slice cached in smem, reused for all b.
// ---------------------------------------------------------------------------
__global__ __launch_bounds__(256) void k_mix(const float* __restrict__ wr,
                                             const float* __restrict__ wi) {
    int m = blockIdx.x;

    __shared__ float2 Ws[64 * 64];   // [c][o] 32 KB
    __shared__ float2 Xs[16 * 64];   // [b][c]  8 KB

    for (int i = threadIdx.x; i < 4096; i += 256)
        Ws[i] = make_float2(wr[(size_t)i * 1024 + m], wi[(size_t)i * 1024 + m]);
    for (int i = threadIdx.x; i < 1024; i += 256) {
        int b = i >> 6, c = i & 63;
        Xs[i] = g_X[((size_t)b * 1024 + m) * 64 + c];
    }
    __syncthreads();

    #pragma unroll
    for (int k = 0; k < 4; k++) {
        int idx = threadIdx.x + k * 256;
        int b = idx >> 6, o = idx & 63;
        float accr = 0.f, acci = 0.f;
        #pragma unroll 8
        for (int c = 0; c < 64; c++) {
            float2 X  = Xs[b * 64 + c];     // broadcast within warp
            float2 Wv = Ws[c * 64 + o];
            accr = fmaf(X.x, Wv.x, fmaf(-X.y, Wv.y, accr));
            acci = fmaf(X.x, Wv.y, fmaf( X.y, Wv.x, acci));
        }
        g_M[((size_t)b * 64 + o) * 1024 + m] = make_float2(accr, acci);
    }
}

// ---------------------------------------------------------------------------
// K4: inverse H-transform.  T[bo,h,ky] = (c_ky/256) * sum_kx M[bo,kx,ky] e^{+2pi i kx h/256}
// grid (1024, 8 h-tiles), block 256. lanes = ky, each thread 4 h.
// ---------------------------------------------------------------------------
__global__ __launch_bounds__(256) void k_invH() {
    int bo = blockIdx.x;
    int h0 = blockIdx.y * 32;

    __shared__ float2 Ms[1024];      // [kx][ky] 8 KB
    for (int i = threadIdx.x; i < 1024; i += 256)
        Ms[i] = g_M[(size_t)bo * 1024 + i];
    __syncthreads();

    int lane = threadIdx.x & 31;     // ky
    int wrp  = threadIdx.x >> 5;     // 0..7
    int ky   = lane;

    float cw[4], sw[4], dcv[4], dsv[4];
    #pragma unroll
    for (int j = 0; j < 4; j++) {
        int h = h0 + wrp * 4 + j;
        sincosf(TWOPI * (float)h / 256.0f, &dsv[j], &dcv[j]);
        cw[j] = 1.0f; sw[j] = 0.0f;  // angle advances by h per kx step
    }

    float tr[4] = {0,0,0,0}, ti[4] = {0,0,0,0};
    for (int kx = 0; kx < 32; kx++) {
        float2 Mv = Ms[kx * 32 + ky];
        #pragma unroll
        for (int j = 0; j < 4; j++) {
            tr[j] = fmaf(Mv.x, cw[j], fmaf(-Mv.y, sw[j], tr[j]));
            ti[j] = fmaf(Mv.x, sw[j], fmaf( Mv.y, cw[j], ti[j]));
            float t = cw[j] * dcv[j] - sw[j] * dsv[j];
            sw[j] = fmaf(sw[j], dcv[j], cw[j] * dsv[j]);
            cw[j] = t;
        }
    }

    float s = (ky == 0 ? 1.0f : 2.0f) * (1.0f / 256.0f);  // hermitian fold + ortho inverse
    #pragma unroll
    for (int j = 0; j < 4; j++) {
        int h = h0 + wrp * 4 + j;
        g_T[((size_t)bo * 256 + h) * 32 + ky] = make_float2(tr[j] * s, ti[j] * s);
    }
}

// ---------------------------------------------------------------------------
// K5: inverse W-transform.  out[bo,h,w] = sum_ky (TR[h,ky] cos(2pi ky w/256) - TI[h,ky] sin(...))
// grid (1024, 8 h-tiles of 32), block 256. Thread: 8 h x 4 w.
// T loads are warp-broadcast float4 (2 ky at a time); twiddle recurrence per w.
// ---------------------------------------------------------------------------
__global__ __launch_bounds__(256) void k_invW(float* __restrict__ out) {
    int bo = blockIdx.x;
    int h0 = blockIdx.y * 32;

    __shared__ float2 Ts[32 * 32];   // 8 KB
    const float2* tp = &g_T[((size_t)bo * 256 + h0) * 32];
    for (int i = threadIdx.x; i < 1024; i += 256) Ts[i] = tp[i];
    __syncthreads();

    int wq = threadIdx.x & 63;       // 64 w-quads
    int hs = threadIdx.x >> 6;       // 4 h-sets (uniform within warp -> broadcast)
    int w0 = wq * 4;
    int hb = hs * 8;

    float acc[8][4];
    #pragma unroll
    for (int j = 0; j < 8; j++)
        #pragma unroll
        for (int u = 0; u < 4; u++) acc[j][u] = 0.f;

    float cw[4], sw[4], dcv[4], dsv[4];
    #pragma unroll
    for (int u = 0; u < 4; u++) {
        sincosf(TWOPI * (float)(w0 + u) / 256.0f, &dsv[u], &dcv[u]);
        cw[u] = 1.0f; sw[u] = 0.0f;
    }

    for (int ky = 0; ky < 32; ky += 2) {
        float4 tv[8];                // (TR,TI) for ky and ky+1, broadcast
        #pragma unroll
        for (int j = 0; j < 8; j++)
            tv[j] = *reinterpret_cast<const float4*>(&Ts[(hb + j) * 32 + ky]);

        #pragma unroll
        for (int u = 0; u < 4; u++) {
            #pragma unroll
            for (int j = 0; j < 8; j++)
                acc[j][u] = fmaf(tv[j].x, cw[u], fmaf(-tv[j].y, sw[u], acc[j][u]));
            float t = cw[u] * dcv[u] - sw[u] * dsv[u];
            sw[u] = fmaf(sw[u], dcv[u], cw[u] * dsv[u]);
            cw[u] = t;
        }
        #pragma unroll
        for (int u = 0; u < 4; u++) {
            #pragma unroll
            for (int j = 0; j < 8; j++)
                acc[j][u] = fmaf(tv[j].z, cw[u], fmaf(-tv[j].w, sw[u], acc[j][u]));
            float t = cw[u] * dcv[u] - sw[u] * dsv[u];
            sw[u] = fmaf(sw[u], dcv[u], cw[u] * dsv[u]);
            cw[u] = t;
        }
    }

    float* op = out + (size_t)bo * HH * WW + (size_t)(h0 + hb) * WW + w0;
    #pragma unroll
    for (int j = 0; j < 8; j++)
        *reinterpret_cast<float4*>(op + (size_t)j * WW) =
            make_float4(acc[j][0], acc[j][1], acc[j][2], acc[j][3]);
}

// ---------------------------------------------------------------------------
extern "C" void kernel_launch(void* const* d_in, const int* in_sizes, int n_in,
                              void* d_out, int out_size) {
    (void)in_sizes; (void)n_in; (void)out_size;
    const float* x  = (const float*)d_in[0];
    const float* wr = (const float*)d_in[1];
    const float* wi = (const float*)d_in[2];
    float* out = (float*)d_out;

    k_fwdW<<<dim3(1024, 8), 128>>>(x);
    k_fwdH<<<dim3(1024, 2), 256>>>();
    k_mix <<<1024, 256>>>(wr, wi);
    k_invH<<<dim3(1024, 8), 256>>>();
    k_invW<<<dim3(1024, 8), 256>>>(out);
}

// round 2
// speedup vs baseline: 1.0088x; 1.0088x over previous
#include <cuda_runtime.h>

#define BB 16
#define CC 64
#define OO 64
#define HH 256
#define WW 256
#define MX 32
#define MY 32

#define TWOPI 6.28318530717958647692f

// Scratch (no allocation allowed -> __device__ globals)
__device__ float2 g_A[BB*CC*MY*HH];   // [bc][ky][h]      67 MB
__device__ float2 g_X[BB*MX*MY*CC];   // [b][mode][c]     8.4 MB
__device__ float2 g_M[BB*OO*MX*MY];   // [bo][mode]       8.4 MB
__device__ float2 g_T[BB*OO*HH*MY];   // [bo][h][ky]      67 MB

// ---------------------------------------------------------------------------
// K1: forward W-transform.  A[bc,ky,h] = (1/256) * sum_w x[bc,h,w] e^{-2pi i ky w/256}
// grid (1024, 8), block 128.  Warp lanes = ky (0..31), each thread 8 h-rows.
// x loads are warp-broadcast float4; twiddle via register recurrence.
// ---------------------------------------------------------------------------
__global__ __launch_bounds__(128) void k_fwdW(const float* __restrict__ x) {
    int bc = blockIdx.x;
    int h0 = blockIdx.y * 32;

    __shared__ float xs[32 * 256];       // 32 KB
    __shared__ float2 st[32][33];        // staging for coalesced transpose store

    const float* xp = x + (size_t)bc * HH * WW + (size_t)h0 * WW;
    for (int i = threadIdx.x; i < 32 * 256; i += 128) xs[i] = xp[i];
    __syncthreads();

    int lane = threadIdx.x & 31;     // ky
    int wrp  = threadIdx.x >> 5;     // 0..3
    int ky   = lane;
    int r0   = wrp * 8;

    float ar[8], ai[8];
    #pragma unroll
    for (int j = 0; j < 8; j++) { ar[j] = 0.f; ai[j] = 0.f; }

    float ds, dc;
    sincosf(-TWOPI * (float)ky / 256.0f, &ds, &dc);
    float cw = 1.0f, sw = 0.0f;      // (cos, sin) of -2pi ky w / 256

    for (int w4 = 0; w4 < 256; w4 += 4) {
        float xc[8][4];
        #pragma unroll
        for (int j = 0; j < 8; j++) {
            float4 v = *reinterpret_cast<const float4*>(&xs[(r0 + j) * 256 + w4]);
            xc[j][0] = v.x; xc[j][1] = v.y; xc[j][2] = v.z; xc[j][3] = v.w;
        }
        #pragma unroll
        for (int u = 0; u < 4; u++) {
            #pragma unroll
            for (int j = 0; j < 8; j++) {
                ar[j] = fmaf(xc[j][u], cw, ar[j]);
                ai[j] = fmaf(xc[j][u], sw, ai[j]);
            }
            float t = cw * dc - sw * ds;
            sw = fmaf(sw, dc, cw * ds);
            cw = t;
        }
    }

    const float sc = 1.0f / 256.0f;  // ortho forward
    #pragma unroll
    for (int j = 0; j < 8; j++)
        st[ky][r0 + j] = make_float2(ar[j] * sc, ai[j] * sc);
    __syncthreads();

    // coalesced write: each warp writes 8 ky-rows of 32 consecutive h
    for (int kq = 0; kq < 8; kq++) {
        int kyy = wrp * 8 + kq;
        g_A[((size_t)bc * 32 + kyy) * 256 + h0 + lane] = st[kyy][lane];
    }
}

// ---------------------------------------------------------------------------
// K2: forward H-transform.  X[b,kx*32+ky,c] = sum_h A[bc,ky,h] e^{-2pi i kx h/256}
// grid (1024, 2 ky-halves), block 256. lanes = kx, warp -> 2 ky.
// ---------------------------------------------------------------------------
__global__ __launch_bounds__(256) void k_fwdH() {
    int bc  = blockIdx.x;
    int kyh = blockIdx.y;            // 0/1 -> ky base 0/16

    __shared__ float2 As[16 * 256];  // 32 KB
    const float2* ap = &g_A[((size_t)bc * 32 + kyh * 16) * 256];
    for (int i = threadIdx.x; i < 16 * 256; i += 256) As[i] = ap[i];
    __syncthreads();

    int lane = threadIdx.x & 31;     // kx
    int wrp  = threadIdx.x >> 5;     // 0..7 -> ky pair
    int kx   = lane;
    int kyl  = wrp * 2;

    float xr0 = 0, xi0 = 0, xr1 = 0, xi1 = 0;
    float ds, dc;
    sincosf(-TWOPI * (float)kx / 256.0f, &ds, &dc);
    float cw = 1.0f, sw = 0.0f;

    for (int h = 0; h < 256; h++) {
        float2 a0 = As[kyl * 256 + h];         // broadcast
        float2 a1 = As[(kyl + 1) * 256 + h];   // broadcast
        // X += A * (cw + i sw)
        xr0 = fmaf(a0.x, cw, fmaf(-a0.y, sw, xr0));
        xi0 = fmaf(a0.x, sw, fmaf( a0.y, cw, xi0));
        xr1 = fmaf(a1.x, cw, fmaf(-a1.y, sw, xr1));
        xi1 = fmaf(a1.x, sw, fmaf( a1.y, cw, xi1));
        float t = cw * dc - sw * ds;
        sw = fmaf(sw, dc, cw * ds);
        cw = t;
    }

    int b = bc >> 6, c = bc & 63;
    int ky = kyh * 16 + kyl;
    g_X[((size_t)b * 1024 + kx * 32 + ky    ) * 64 + c] = make_float2(xr0, xi0);
    g_X[((size_t)b * 1024 + kx * 32 + ky + 1) * 64 + c] = make_float2(xr1, xi1);
}

// ---------------------------------------------------------------------------
// K3: channel mix.  M[b,o,m] = sum_c X[b,c,m] * (Wr + i Wi)[c,o,m]
// grid (1024 modes), block 256. Weight slice cached in smem, reused for all b.
// ---------------------------------------------------------------------------
__global__ __launch_bounds__(256) void k_mix(const float* __restrict__ wr,
                                             const float* __restrict__ wi) {
    int m = blockIdx.x;

    __shared__ float2 Ws[64 * 64];   // [c][o] 32 KB
    __shared__ float2 Xs[16 * 64];   // [b][c]  8 KB

    for (int i = threadIdx.x; i < 4096; i += 256)
        Ws[i] = make_float2(wr[(size_t)i * 1024 + m], wi[(size_t)i * 1024 + m]);
    for (int i = threadIdx.x; i < 1024; i += 256) {
        int b = i >> 6, c = i & 63;
        Xs[i] = g_X[((size_t)b * 1024 + m) * 64 + c];
    }
    __syncthreads();

    #pragma unroll
    for (int k = 0; k < 4; k++) {
        int idx = threadIdx.x + k * 256;
        int b = idx >> 6, o = idx & 63;
        float accr = 0.f, acci = 0.f;
        #pragma unroll 8
        for (int c = 0; c < 64; c++) {
            float2 X  = Xs[b * 64 + c];     // broadcast within warp
            float2 Wv = Ws[c * 64 + o];
            accr = fmaf(X.x, Wv.x, fmaf(-X.y, Wv.y, accr));
            acci = fmaf(X.x, Wv.y, fmaf( X.y, Wv.x, acci));
        }
        g_M[((size_t)b * 64 + o) * 1024 + m] = make_float2(accr, acci);
    }
}

// ---------------------------------------------------------------------------
// K4: inverse H-transform.  T[bo,h,ky] = (c_ky/256) * sum_kx M[bo,kx,ky] e^{+2pi i kx h/256}
// grid (1024, 8 h-tiles), block 256. lanes = ky, each thread 4 h.
// ---------------------------------------------------------------------------
__global__ __launch_bounds__(256) void k_invH() {
    int bo = blockIdx.x;
    int h0 = blockIdx.y * 32;

    __shared__ float2 Ms[1024];      // [kx][ky] 8 KB
    for (int i = threadIdx.x; i < 1024; i += 256)
        Ms[i] = g_M[(size_t)bo * 1024 + i];
    __syncthreads();

    int lane = threadIdx.x & 31;     // ky
    int wrp  = threadIdx.x >> 5;     // 0..7
    int ky   = lane;

    float cw[4], sw[4], dcv[4], dsv[4];
    #pragma unroll
    for (int j = 0; j < 4; j++) {
        int h = h0 + wrp * 4 + j;
        sincosf(TWOPI * (float)h / 256.0f, &dsv[j], &dcv[j]);
        cw[j] = 1.0f; sw[j] = 0.0f;  // angle advances by h per kx step
    }

    float tr[4] = {0,0,0,0}, ti[4] = {0,0,0,0};
    for (int kx = 0; kx < 32; kx++) {
        float2 Mv = Ms[kx * 32 + ky];
        #pragma unroll
        for (int j = 0; j < 4; j++) {
            tr[j] = fmaf(Mv.x, cw[j], fmaf(-Mv.y, sw[j], tr[j]));
            ti[j] = fmaf(Mv.x, sw[j], fmaf( Mv.y, cw[j], ti[j]));
            float t = cw[j] * dcv[j] - sw[j] * dsv[j];
            sw[j] = fmaf(sw[j], dcv[j], cw[j] * dsv[j]);
            cw[j] = t;
        }
    }

    float s = (ky == 0 ? 1.0f : 2.0f) * (1.0f / 256.0f);  // hermitian fold + ortho inverse
    #pragma unroll
    for (int j = 0; j < 4; j++) {
        int h = h0 + wrp * 4 + j;
        g_T[((size_t)bo * 256 + h) * 32 + ky] = make_float2(tr[j] * s, ti[j] * s);
    }
}

// ---------------------------------------------------------------------------
// K5: inverse W-transform.  out[bo,h,w] = sum_ky (TR[h,ky] cos(2pi ky w/256) - TI[h,ky] sin(...))
// grid (1024, 8 h-tiles of 32), block 256. Thread: 8 h x 4 w.
// T loads are warp-broadcast float4 (2 ky at a time); twiddle recurrence per w.
// ---------------------------------------------------------------------------
__global__ __launch_bounds__(256) void k_invW(float* __restrict__ out) {
    int bo = blockIdx.x;
    int h0 = blockIdx.y * 32;

    __shared__ float2 Ts[32 * 32];   // 8 KB
    const float2* tp = &g_T[((size_t)bo * 256 + h0) * 32];
    for (int i = threadIdx.x; i < 1024; i += 256) Ts[i] = tp[i];
    __syncthreads();

    int wq = threadIdx.x & 63;       // 64 w-quads
    int hs = threadIdx.x >> 6;       // 4 h-sets (uniform within warp -> broadcast)
    int w0 = wq * 4;
    int hb = hs * 8;

    float acc[8][4];
    #pragma unroll
    for (int j = 0; j < 8; j++)
        #pragma unroll
        for (int u = 0; u < 4; u++) acc[j][u] = 0.f;

    float cw[4], sw[4], dcv[4], dsv[4];
    #pragma unroll
    for (int u = 0; u < 4; u++) {
        sincosf(TWOPI * (float)(w0 + u) / 256.0f, &dsv[u], &dcv[u]);
        cw[u] = 1.0f; sw[u] = 0.0f;
    }

    for (int ky = 0; ky < 32; ky += 2) {
        float4 tv[8];                // (TR,TI) for ky and ky+1, broadcast
        #pragma unroll
        for (int j = 0; j < 8; j++)
            tv[j] = *reinterpret_cast<const float4*>(&Ts[(hb + j) * 32 + ky]);

        #pragma unroll
        for (int u = 0; u < 4; u++) {
            #pragma unroll
            for (int j = 0; j < 8; j++)
                acc[j][u] = fmaf(tv[j].x, cw[u], fmaf(-tv[j].y, sw[u], acc[j][u]));
            float t = cw[u] * dcv[u] - sw[u] * dsv[u];
            sw[u] = fmaf(sw[u], dcv[u], cw[u] * dsv[u]);
            cw[u] = t;
        }
        #pragma unroll
        for (int u = 0; u < 4; u++) {
            #pragma unroll
            for (int j = 0; j < 8; j++)
                acc[j][u] = fmaf(tv[j].z, cw[u], fmaf(-tv[j].w, sw[u], acc[j][u]));
            float t = cw[u] * dcv[u] - sw[u] * dsv[u];
            sw[u] = fmaf(sw[u], dcv[u], cw[u] * dsv[u]);
            cw[u] = t;
        }
    }

    float* op = out + (size_t)bo * HH * WW + (size_t)(h0 + hb) * WW + w0;
    #pragma unroll
    for (int j = 0; j < 8; j++)
        *reinterpret_cast<float4*>(op + (size_t)j * WW) =
            make_float4(acc[j][0], acc[j][1], acc[j][2], acc[j][3]);
}

// ---------------------------------------------------------------------------
extern "C" void kernel_launch(void* const* d_in, const int* in_sizes, int n_in,
                              void* d_out, int out_size) {
    (void)in_sizes; (void)n_in; (void)out_size;
    const float* x  = (const float*)d_in[0];
    const float* wr = (const float*)d_in[1];
    const float* wi = (const float*)d_in[2];
    float* out = (float*)d_out;

    k_fwdW<<<dim3(1024, 8), 128>>>(x);
    k_fwdH<<<dim3(1024, 2), 256>>>();
    k_mix <<<1024, 256>>>(wr, wi);
    k_invH<<<dim3(1024, 8), 256>>>();
    k_invW<<<dim3(1024, 8), 256>>>(out);
}

// round 3
// speedup vs baseline: 1.2812x; 1.2700x over previous
#include <cuda_runtime.h>

#define TWOPI 6.28318530717958647692f

// Scratch (no allocation allowed -> __device__ globals)
__device__ float2 g_A[16*64*32*256];   // [bc][ky][h]      67 MB
__device__ float2 g_X[16*32*32*64];    // [b][mode][c]     8.4 MB
__device__ float2 g_M[16*64*32*32];    // [bo][mode]       8.4 MB
__device__ float2 g_T[16*64*256*32];   // [bo][h][ky]      67 MB

// ---------------------------------------------------------------------------
// K1: forward W-transform, hermitian input fold.
//   A[ky] = (1/256)[ x0 + sum_{p=1..128} (x[p]+x[256-p]) c(ky p) - i (x[p]-x[256-p]) s(ky p) ]
// block 128 = 4 warps; lane = ky, each thread 8 h-rows; twiddle recurrence for e^{-i}.
// ---------------------------------------------------------------------------
__global__ __launch_bounds__(128) void k_fwdW(const float* __restrict__ x) {
    __shared__ float2 sf[32][128];   // (xp, xm) for p = f+1, 32 KB
    __shared__ float  sx0[32];
    __shared__ float2 st[32][33];
    int bc = blockIdx.x, h0 = blockIdx.y * 32;
    const float* xr = x + (size_t)bc * 65536 + (size_t)h0 * 256;

    for (int i = threadIdx.x; i < 4096; i += 128) {
        int h = i >> 7, f = i & 127, p = f + 1;
        float a = xr[h * 256 + p];
        if (p == 128) sf[h][f] = make_float2(a, 0.f);
        else { float b = xr[h * 256 + 256 - p]; sf[h][f] = make_float2(a + b, a - b); }
    }
    if (threadIdx.x < 32) sx0[threadIdx.x] = xr[threadIdx.x * 256];
    __syncthreads();

    int lane = threadIdx.x & 31, wrp = threadIdx.x >> 5, r0 = wrp * 8;
    int ky = lane;
    float ar[8], ai[8];
    #pragma unroll
    for (int j = 0; j < 8; j++) { ar[j] = sx0[r0 + j]; ai[j] = 0.f; }

    float ds, dc; sincosf(-TWOPI * (float)ky * (1.0f/256.0f), &ds, &dc);
    float cw = dc, sw = ds;                 // (cos, -sin) at p = 1
    for (int g = 0; g < 64; g++) {
        float4 v[8];                        // (xp,xm) for p=2g+1 and (xp,xm) for p=2g+2
        #pragma unroll
        for (int j = 0; j < 8; j++)
            v[j] = *reinterpret_cast<const float4*>(&sf[r0 + j][g * 2]);
        #pragma unroll
        for (int j = 0; j < 8; j++) {
            ar[j] = fmaf(v[j].x, cw, ar[j]);
            ai[j] = fmaf(v[j].y, sw, ai[j]);
        }
        { float t = cw*dc - sw*ds; sw = fmaf(sw, dc, cw*ds); cw = t; }
        #pragma unroll
        for (int j = 0; j < 8; j++) {
            ar[j] = fmaf(v[j].z, cw, ar[j]);
            ai[j] = fmaf(v[j].w, sw, ai[j]);
        }
        { float t = cw*dc - sw*ds; sw = fmaf(sw, dc, cw*ds); cw = t; }
    }

    const float sc = 1.0f / 256.0f;         // ortho forward
    #pragma unroll
    for (int j = 0; j < 8; j++)
        st[ky][r0 + j] = make_float2(ar[j] * sc, ai[j] * sc);
    __syncthreads();

    float2* A = &g_A[(size_t)bc * 8192];
    for (int kq = 0; kq < 8; kq++) {
        int kyy = wrp * 8 + kq;
        A[kyy * 256 + h0 + lane] = st[kyy][lane];
    }
}

// ---------------------------------------------------------------------------
// K2: forward H-transform with input fold over (h, 256-h), 2 smem phases over p.
// block 256; lane = kx, warp -> 4 ky. Term: Re += Apr*cw - Ami*sw, Im += Api*cw + Amr*sw
// (cw,sw) = e^{-2pi i kx p/256}.
// ---------------------------------------------------------------------------
__global__ __launch_bounds__(256) void k_fwdH() {
    __shared__ float4 sfold[32][64];        // (Apr,Api,Amr,Ami), 32 KB
    int bc = blockIdx.x;
    const float2* A = &g_A[(size_t)bc * 8192];
    int kx = threadIdx.x & 31, wrp = threadIdx.x >> 5, kyb = wrp * 4;

    float xr[4], xi[4];
    #pragma unroll
    for (int k = 0; k < 4; k++) { float2 a0 = A[(kyb + k) * 256]; xr[k] = a0.x; xi[k] = a0.y; }

    float dsb, dcb; sincosf(-TWOPI * (float)kx * (1.0f/256.0f), &dsb, &dcb);

    #pragma unroll
    for (int ph = 0; ph < 2; ph++) {
        __syncthreads();
        for (int i = threadIdx.x; i < 2048; i += 256) {
            int kyy = i >> 6, f = i & 63, p = ph * 64 + f + 1;
            float2 a = A[kyy * 256 + p];
            if (p == 128) sfold[kyy][f] = make_float4(a.x, a.y, 0.f, 0.f);
            else {
                float2 b = A[kyy * 256 + 256 - p];
                sfold[kyy][f] = make_float4(a.x + b.x, a.y + b.y, a.x - b.x, a.y - b.y);
            }
        }
        __syncthreads();
        float s0, c0; sincosf(-TWOPI * (float)(kx * (ph * 64 + 1)) * (1.0f/256.0f), &s0, &c0);
        float cw = c0, sw = s0;
        #pragma unroll 4
        for (int f = 0; f < 64; f++) {
            float4 v0 = sfold[kyb + 0][f];
            float4 v1 = sfold[kyb + 1][f];
            float4 v2 = sfold[kyb + 2][f];
            float4 v3 = sfold[kyb + 3][f];
            xr[0] = fmaf(v0.x, cw, fmaf(-v0.w, sw, xr[0])); xi[0] = fmaf(v0.y, cw, fmaf(v0.z, sw, xi[0]));
            xr[1] = fmaf(v1.x, cw, fmaf(-v1.w, sw, xr[1])); xi[1] = fmaf(v1.y, cw, fmaf(v1.z, sw, xi[1]));
            xr[2] = fmaf(v2.x, cw, fmaf(-v2.w, sw, xr[2])); xi[2] = fmaf(v2.y, cw, fmaf(v2.z, sw, xi[2]));
            xr[3] = fmaf(v3.x, cw, fmaf(-v3.w, sw, xr[3])); xi[3] = fmaf(v3.y, cw, fmaf(v3.z, sw, xi[3]));
            { float t = cw*dcb - sw*dsb; sw = fmaf(sw, dcb, cw*dsb); cw = t; }
        }
    }

    int b = bc >> 6, c = bc & 63;
    #pragma unroll
    for (int k = 0; k < 4; k++)
        g_X[((size_t)b * 1024 + kx * 32 + kyb + k) * 64 + c] = make_float2(xr[k], xi[k]);
}

// ---------------------------------------------------------------------------
// K3: channel mix.  M[b,o,m] = sum_c X[b,c,m] * (Wr + i Wi)[c,o,m]   (unchanged)
// ---------------------------------------------------------------------------
__global__ __launch_bounds__(256) void k_mix(const float* __restrict__ wr,
                                             const float* __restrict__ wi) {
    int m = blockIdx.x;
    __shared__ float2 Ws[64 * 64];
    __shared__ float2 Xs[16 * 64];

    for (int i = threadIdx.x; i < 4096; i += 256)
        Ws[i] = make_float2(wr[(size_t)i * 1024 + m], wi[(size_t)i * 1024 + m]);
    for (int i = threadIdx.x; i < 1024; i += 256) {
        int b = i >> 6, c = i & 63;
        Xs[i] = g_X[((size_t)b * 1024 + m) * 64 + c];
    }
    __syncthreads();

    #pragma unroll
    for (int k = 0; k < 4; k++) {
        int idx = threadIdx.x + k * 256;
        int b = idx >> 6, o = idx & 63;
        float accr = 0.f, acci = 0.f;
        #pragma unroll 8
        for (int c = 0; c < 64; c++) {
            float2 X  = Xs[b * 64 + c];
            float2 Wv = Ws[c * 64 + o];
            accr = fmaf(X.x, Wv.x, fmaf(-X.y, Wv.y, accr));
            acci = fmaf(X.x, Wv.y, fmaf( X.y, Wv.x, acci));
        }
        g_M[((size_t)b * 64 + o) * 1024 + m] = make_float2(accr, acci);
    }
}

// ---------------------------------------------------------------------------
// K4: inverse H-transform, kx-parity fold: E = sum_{even kx}, O = sum_{odd kx};
//   T[h] = (E+O)*s, T[h+128] = (E-O)*s, s = (ky==0?1:2)/256.
// grid (1024, 4); block 256: thread = (h_local = tid>>3, kyg = tid&7 -> 4 ky).
// ---------------------------------------------------------------------------
__global__ __launch_bounds__(256) void k_invH() {
    __shared__ float2 Ms[32][32];           // [kx][ky]
    int bo = blockIdx.x, h0 = blockIdx.y * 32;
    for (int i = threadIdx.x; i < 1024; i += 256)
        (&Ms[0][0])[i] = g_M[(size_t)bo * 1024 + i];
    __syncthreads();

    int hl = threadIdx.x >> 3, kyg = threadIdx.x & 7, ky0 = kyg * 4;
    int h = h0 + hl;

    float Er[4] = {0,0,0,0}, Ei[4] = {0,0,0,0};
    float Qr[4] = {0,0,0,0}, Qi[4] = {0,0,0,0};   // odd-kx sums
    float ds, dc; sincosf(TWOPI * (float)h * (1.0f/256.0f), &ds, &dc);
    float cw = 1.f, sw = 0.f;                     // e^{+2pi i kx h/256} at kx=0

    for (int kx = 0; kx < 32; kx += 2) {
        float4 a = *reinterpret_cast<const float4*>(&Ms[kx][ky0]);
        float4 b = *reinterpret_cast<const float4*>(&Ms[kx][ky0 + 2]);
        Er[0] = fmaf(a.x, cw, fmaf(-a.y, sw, Er[0])); Ei[0] = fmaf(a.x, sw, fmaf(a.y, cw, Ei[0]));
        Er[1] = fmaf(a.z, cw, fmaf(-a.w, sw, Er[1])); Ei[1] = fmaf(a.z, sw, fmaf(a.w, cw, Ei[1]));
        Er[2] = fmaf(b.x, cw, fmaf(-b.y, sw, Er[2])); Ei[2] = fmaf(b.x, sw, fmaf(b.y, cw, Ei[2]));
        Er[3] = fmaf(b.z, cw, fmaf(-b.w, sw, Er[3])); Ei[3] = fmaf(b.z, sw, fmaf(b.w, cw, Ei[3]));
        { float t = cw*dc - sw*ds; sw = fmaf(sw, dc, cw*ds); cw = t; }
        float4 e = *reinterpret_cast<const float4*>(&Ms[kx + 1][ky0]);
        float4 f = *reinterpret_cast<const float4*>(&Ms[kx + 1][ky0 + 2]);
        Qr[0] = fmaf(e.x, cw, fmaf(-e.y, sw, Qr[0])); Qi[0] = fmaf(e.x, sw, fmaf(e.y, cw, Qi[0]));
        Qr[1] = fmaf(e.z, cw, fmaf(-e.w, sw, Qr[1])); Qi[1] = fmaf(e.z, sw, fmaf(e.w, cw, Qi[1]));
        Qr[2] = fmaf(f.x, cw, fmaf(-f.y, sw, Qr[2])); Qi[2] = fmaf(f.x, sw, fmaf(f.y, cw, Qi[2]));
        Qr[3] = fmaf(f.z, cw, fmaf(-f.w, sw, Qr[3])); Qi[3] = fmaf(f.z, sw, fmaf(f.w, cw, Qi[3]));
        { float t = cw*dc - sw*ds; sw = fmaf(sw, dc, cw*ds); cw = t; }
    }

    float2 o1[4], o2[4];
    #pragma unroll
    for (int k = 0; k < 4; k++) {
        float s = ((ky0 + k) == 0 ? 1.0f : 2.0f) * (1.0f/256.0f);
        o1[k] = make_float2((Er[k] + Qr[k]) * s, (Ei[k] + Qi[k]) * s);
        o2[k] = make_float2((Er[k] - Qr[k]) * s, (Ei[k] - Qi[k]) * s);
    }
    float2* T1 = &g_T[((size_t)bo * 256 + h) * 32 + ky0];
    float2* T2 = &g_T[((size_t)bo * 256 + h + 128) * 32 + ky0];
    *reinterpret_cast<float4*>(T1)     = make_float4(o1[0].x, o1[0].y, o1[1].x, o1[1].y);
    *reinterpret_cast<float4*>(T1 + 2) = make_float4(o1[2].x, o1[2].y, o1[3].x, o1[3].y);
    *reinterpret_cast<float4*>(T2)     = make_float4(o2[0].x, o2[0].y, o2[1].x, o2[1].y);
    *reinterpret_cast<float4*>(T2 + 2) = make_float4(o2[2].x, o2[2].y, o2[3].x, o2[3].y);
}

// ---------------------------------------------------------------------------
// K5: inverse W-transform, output fold over (w, 256-w):
//   U = sum_ky TR*cos, V = sum_ky TI*sin; out[w]=U-V, out[256-w]=U+V;
//   out[0]=U(0); out[128]=sum_ky TR*(-1)^ky.
// grid (1024, 16 h-tiles of 16); block 256 = 128 w-slots x 2 h-groups of 8 h.
// ---------------------------------------------------------------------------
__global__ __launch_bounds__(256) void k_invW(float* __restrict__ out) {
    __shared__ float2 Ts[16][32];
    __shared__ float  Os[16][256];
    int bo = blockIdx.x, h0 = blockIdx.y * 16;

    for (int i = threadIdx.x; i < 512; i += 256)
        (&Ts[0][0])[i] = g_T[((size_t)bo * 256 + h0) * 32 + i];
    __syncthreads();

    int w = threadIdx.x & 127, hg = threadIdx.x >> 7, hb = hg * 8;
    float U[8], V[8], U128[8];
    #pragma unroll
    for (int j = 0; j < 8; j++) { U[j] = 0.f; V[j] = 0.f; U128[j] = 0.f; }

    float ds, dc; sincosf(TWOPI * (float)w * (1.0f/256.0f), &ds, &dc);
    float cw = 1.f, sw = 0.f;

    for (int ky = 0; ky < 32; ky += 2) {
        float4 tv[8];                       // (TR, TI) for ky and ky+1
        #pragma unroll
        for (int j = 0; j < 8; j++)
            tv[j] = *reinterpret_cast<const float4*>(&Ts[hb + j][ky]);
        #pragma unroll
        for (int j = 0; j < 8; j++) { U[j] = fmaf(tv[j].x, cw, U[j]); V[j] = fmaf(tv[j].y, sw, V[j]); }
        { float t = cw*dc - sw*ds; sw = fmaf(sw, dc, cw*ds); cw = t; }
        #pragma unroll
        for (int j = 0; j < 8; j++) { U[j] = fmaf(tv[j].z, cw, U[j]); V[j] = fmaf(tv[j].w, sw, V[j]); }
        { float t = cw*dc - sw*ds; sw = fmaf(sw, dc, cw*ds); cw = t; }
        if (w == 0) {
            #pragma unroll
            for (int j = 0; j < 8; j++) U128[j] += tv[j].x - tv[j].z;
        }
    }

    #pragma unroll
    for (int j = 0; j < 8; j++) {
        Os[hb + j][w] = U[j] - V[j];
        if (w) Os[hb + j][256 - w] = U[j] + V[j];
        else   Os[hb + j][128]     = U128[j];
    }
    __syncthreads();

    float* op = out + (size_t)bo * 65536 + (size_t)h0 * 256;
    for (int i = threadIdx.x; i < 1024; i += 256) {
        int r = i >> 6, c4 = (i & 63) * 4;
        *reinterpret_cast<float4*>(op + r * 256 + c4) =
            *reinterpret_cast<const float4*>(&Os[r][c4]);
    }
}

// ---------------------------------------------------------------------------
extern "C" void kernel_launch(void* const* d_in, const int* in_sizes, int n_in,
                              void* d_out, int out_size) {
    (void)in_sizes; (void)n_in; (void)out_size;
    const float* x  = (const float*)d_in[0];
    const float* wr = (const float*)d_in[1];
    const float* wi = (const float*)d_in[2];
    float* out = (float*)d_out;

    k_fwdW<<<dim3(1024, 8), 128>>>(x);
    k_fwdH<<<1024, 256>>>();
    k_mix <<<1024, 256>>>(wr, wi);
    k_invH<<<dim3(1024, 4), 256>>>();
    k_invW<<<dim3(1024, 16), 256>>>(out);
}